// round 16
// baseline (speedup 1.0000x reference)
#include <cuda_runtime.h>
#include <cuda_fp16.h>
#include <cstdint>

#define NUM_E 8
#define DIM_H 2880
#define DIM_I 2880
#define DIM_T 1024
#define DIM_F 5760
#define NT    160

__device__ __half g_xh_hi[DIM_T * DIM_H];
__device__ __half g_xh_lo[DIM_T * DIM_H];
__device__ __half g_act_hi[(size_t)NUM_E * DIM_T * DIM_I];
__device__ __half g_act_lo[(size_t)NUM_E * DIM_T * DIM_I];
__device__ __half g_wgu[(size_t)NUM_E * DIM_F * DIM_H];
__device__ __half g_wd[(size_t)NUM_E * DIM_H * DIM_I];

__constant__ unsigned short c_fp4[16] = {
    0x0000, 0x3800, 0x3C00, 0x3E00, 0x4000, 0x4200, 0x4400, 0x4600,
    0x8000, 0xB800, 0xBC00, 0xBE00, 0xC000, 0xC200, 0xC400, 0xC600};

// Dequant body: one 256-thread block handles 256 groups of 32 weights.
__device__ __forceinline__ void deq_body(const int4* __restrict__ blk,
                                         const int* __restrict__ scl, int ngroups,
                                         int gb, __half* __restrict__ outp,
                                         void* smem) {
    __half2* lut = reinterpret_cast<__half2*>(smem);
    int t = threadIdx.x;
    lut[t] = __halves2half2(__ushort_as_half(c_fp4[t & 15]),
                            __ushort_as_half(c_fp4[(t >> 4) & 15]));
    __syncthreads();
    int g = gb * 256 + t;
    if (g >= ngroups) return;
    int row = g / 90, grp = g % 90;
    int4 v0 = blk[g * 4 + 0], v1 = blk[g * 4 + 1], v2 = blk[g * 4 + 2],
         v3 = blk[g * 4 + 3];
    int sc = scl[g];
    __half2 s2 = __half2half2(__ushort_as_half((unsigned short)((sc - 112) << 10)));
    int b[16] = {v0.x, v0.y, v0.z, v0.w, v1.x, v1.y, v1.z, v1.w,
                 v2.x, v2.y, v2.z, v2.w, v3.x, v3.y, v3.z, v3.w};
    __half2 o[16];
#pragma unroll
    for (int j = 0; j < 16; j++) o[j] = __hmul2(lut[b[j] & 255], s2);
    uint4* dst = reinterpret_cast<uint4*>(outp + (size_t)row * 2880 + grp * 32);
#pragma unroll
    for (int j = 0; j < 4; j++) dst[j] = *reinterpret_cast<uint4*>(&o[4 * j]);
}

// x -> fp16 hi/lo split; block b covers 1024 float4 (4 per thread, coalesced)
__device__ __forceinline__ void convert_body(const float4* __restrict__ x, int n4,
                                             int b) {
#pragma unroll
    for (int j = 0; j < 4; j++) {
        int i = b * 1024 + j * 256 + threadIdx.x;
        if (i < n4) {
            float4 v = x[i];
            float f[4] = {v.x, v.y, v.z, v.w};
            __half h[4], l[4];
#pragma unroll
            for (int q = 0; q < 4; q++) {
                h[q] = __float2half_rn(f[q]);
                l[q] = __float2half_rn(f[q] - __half2float(h[q]));
            }
            reinterpret_cast<__half2*>(g_xh_hi)[2 * i]     = __halves2half2(h[0], h[1]);
            reinterpret_cast<__half2*>(g_xh_hi)[2 * i + 1] = __halves2half2(h[2], h[3]);
            reinterpret_cast<__half2*>(g_xh_lo)[2 * i]     = __halves2half2(l[0], l[1]);
            reinterpret_cast<__half2*>(g_xh_lo)[2 * i + 1] = __halves2half2(l[2], l[3]);
        }
    }
}

#define DEQ1_BLOCKS 16200 /* 8*5760*90 / 256 */
#define CONV_BLOCKS 720   /* 737280 float4 / 1024 */

// Fused prep: gate_up dequant + x hi/lo convert in one launch.
__global__ __launch_bounds__(256) void k_prep(const int4* __restrict__ gub,
                                              const int* __restrict__ gus,
                                              const float4* __restrict__ x) {
    __shared__ __half2 lut[256];
    int b = blockIdx.x;
    if (b < DEQ1_BLOCKS)
        deq_body(gub, gus, NUM_E * DIM_F * 90, b, g_wgu, lut);
    else
        convert_body(x, DIM_T * DIM_H / 4, b - DEQ1_BLOCKS);
}

// ---------------------------------------------------------------------------
// HMMA GEMM: pre-dequant fp16 B, split-precision A (hi+lo), 3-stage cp.async,
// single sync per k-tile, warp-parity kk/load stagger. Tile 128x160x32,
// 8 warps (2M x 4N), warp 64x40, 2 CTAs/SM.
// EPI==1: GLU -> g_act hi/lo; extra grid-z slices backfill: down-proj dequant
//         + d_out zeroing (both must precede GEMM2).
// EPI==2: vector red.global.add.v2.f32 into d_out.
// ---------------------------------------------------------------------------
#define LDS 40
#define SMEM_BYTES ((2 * 128 + NT) * LDS * 2 * 3)
#define DEQ2_BLOCKS 8100  /* 8*2880*90 / 256 */
#define ZERO_BLOCKS 720   /* 737280 float4 / 1024 */
#define G1X 36            /* DIM_F / NT */
#define G1Y 8             /* DIM_T / 128 */
#define BF_TOTAL (DEQ2_BLOCKS + ZERO_BLOCKS)
#define BF_SLICES 31      /* ceil(8820 / 288) */

template <int EPI>
__global__ __launch_bounds__(256, 2) void gemm_glu(const float* __restrict__ bias,
                                                   const float* __restrict__ rw,
                                                   float* __restrict__ outp,
                                                   const int4* __restrict__ dblk,
                                                   const int* __restrict__ dscl) {
    constexpr int NW = (EPI == 1) ? DIM_F : DIM_H;
    constexpr int K  = 2880;
    constexpr int KT = K / 32;  // 90

    extern __shared__ __align__(16) char smem_raw[];

    if (EPI == 1 && blockIdx.z >= NUM_E) {
        int b = (blockIdx.z - NUM_E) * (G1X * G1Y) + blockIdx.y * G1X + blockIdx.x;
        if (b < DEQ2_BLOCKS) {
            deq_body(dblk, dscl, NUM_E * DIM_H * 90, b, g_wd, smem_raw);
        } else if (b < BF_TOTAL) {
            int zb = b - DEQ2_BLOCKS;
            float4* o4 = reinterpret_cast<float4*>(outp);
#pragma unroll
            for (int j = 0; j < 4; j++) {
                int i = zb * 1024 + j * 256 + threadIdx.x;
                if (i < DIM_T * DIM_H / 4) o4[i] = make_float4(0.f, 0.f, 0.f, 0.f);
            }
        }
        return;
    }

    const int e    = blockIdx.z;
    const int n0   = blockIdx.x * NT;
    const int m0   = blockIdx.y * 128;
    const int tid  = threadIdx.x;
    const int lane = tid & 31;
    const int wid  = tid >> 5;
    const int wm   = wid >> 2;
    const int wn   = wid & 3;
    const int wpar = wid & 1;

    __half* AsH = reinterpret_cast<__half*>(smem_raw);
    __half* AsL = AsH + 3 * 128 * LDS;
    __half* Bs  = AsL + 3 * 128 * LDS;

#define SM_AH(s, r, c) AsH[((s)*128 + (r)) * LDS + (c)]
#define SM_AL(s, r, c) AsL[((s)*128 + (r)) * LDS + (c)]
#define SM_B(s, r, c)  Bs[((s)*NT + (r)) * LDS + (c)]

    const __half* AgH = (EPI == 1) ? g_xh_hi : g_act_hi + (size_t)e * DIM_T * K;
    const __half* AgL = (EPI == 1) ? g_xh_lo : g_act_lo + (size_t)e * DIM_T * K;
    const __half* BW  = ((EPI == 1) ? g_wgu : g_wd) + ((size_t)e * NW + n0) * K;

    auto load_A = [&](int st, int kt) {
#pragma unroll
        for (int i = tid; i < 512; i += 256) {
            int r = i >> 2, c = (i & 3) * 8;
            unsigned dh = (unsigned)__cvta_generic_to_shared(&SM_AH(st, r, c));
            asm volatile("cp.async.cg.shared.global [%0],[%1],16;" ::"r"(dh),
                         "l"(AgH + (size_t)(m0 + r) * K + kt * 32 + c));
            unsigned dl = (unsigned)__cvta_generic_to_shared(&SM_AL(st, r, c));
            asm volatile("cp.async.cg.shared.global [%0],[%1],16;" ::"r"(dl),
                         "l"(AgL + (size_t)(m0 + r) * K + kt * 32 + c));
        }
    };
    auto load_B = [&](int st, int kt) {
#pragma unroll 1
        for (int i = tid; i < NT * 4; i += 256) {
            int r = i >> 2, c = (i & 3) * 8;
            unsigned db = (unsigned)__cvta_generic_to_shared(&SM_B(st, r, c));
            asm volatile("cp.async.cg.shared.global [%0],[%1],16;" ::"r"(db),
                         "l"(BW + (size_t)r * K + kt * 32 + c));
        }
    };
    auto load_stage = [&](int st, int kt) {
        if (wpar) {
            load_B(st, kt);
            load_A(st, kt);
        } else {
            load_A(st, kt);
            load_B(st, kt);
        }
        asm volatile("cp.async.commit_group;");
    };

    float acc[4][5][4];
#pragma unroll
    for (int i = 0; i < 4; i++)
#pragma unroll
        for (int j = 0; j < 5; j++)
#pragma unroll
            for (int c = 0; c < 4; c++) acc[i][j][c] = 0.f;

    const int brow = wn * 40 + (lane & 7);
    const int bcol = ((lane >> 3) & 1) * 8;
    const int arow = wm * 64 + (lane & 15);
    const int acol = (lane >> 4) * 8;

    load_stage(0, 0);
    load_stage(1, 1);

#pragma unroll 1
    for (int kt = 0; kt < KT; ++kt) {
        const int cur = kt % 3;
        if (kt + 1 < KT)
            asm volatile("cp.async.wait_group 1;");
        else
            asm volatile("cp.async.wait_group 0;");
        __syncthreads();
        if (kt + 2 < KT) load_stage((kt + 2) % 3, kt + 2);

#pragma unroll
        for (int kx = 0; kx < 2; ++kx) {
            const int kk = kx ^ wpar;  // warp-parity stagger: anti-phase LDSM
            unsigned bfr[5][2];
#pragma unroll
            for (int ni = 0; ni < 5; ni++) {
                unsigned sa = (unsigned)__cvta_generic_to_shared(
                    &SM_B(cur, brow + ni * 8, kk * 16 + bcol));
                asm volatile("ldmatrix.sync.aligned.m8n8.x2.shared.b16 {%0,%1},[%2];"
                             : "=r"(bfr[ni][0]), "=r"(bfr[ni][1])
                             : "r"(sa));
            }
#pragma unroll
            for (int mi = 0; mi < 4; mi++) {
                unsigned ah[4], al[4];
                unsigned sh = (unsigned)__cvta_generic_to_shared(
                    &SM_AH(cur, arow + mi * 16, kk * 16 + acol));
                asm volatile("ldmatrix.sync.aligned.m8n8.x4.shared.b16 {%0,%1,%2,%3},[%4];"
                             : "=r"(ah[0]), "=r"(ah[1]), "=r"(ah[2]), "=r"(ah[3])
                             : "r"(sh));
                unsigned sl = (unsigned)__cvta_generic_to_shared(
                    &SM_AL(cur, arow + mi * 16, kk * 16 + acol));
                asm volatile("ldmatrix.sync.aligned.m8n8.x4.shared.b16 {%0,%1,%2,%3},[%4];"
                             : "=r"(al[0]), "=r"(al[1]), "=r"(al[2]), "=r"(al[3])
                             : "r"(sl));
#pragma unroll
                for (int ni = 0; ni < 5; ni++) {
                    asm volatile(
                        "mma.sync.aligned.m16n8k16.row.col.f32.f16.f16.f32 "
                        "{%0,%1,%2,%3},{%4,%5,%6,%7},{%8,%9},{%0,%1,%2,%3};"
                        : "+f"(acc[mi][ni][0]), "+f"(acc[mi][ni][1]),
                          "+f"(acc[mi][ni][2]), "+f"(acc[mi][ni][3])
                        : "r"(ah[0]), "r"(ah[1]), "r"(ah[2]), "r"(ah[3]),
                          "r"(bfr[ni][0]), "r"(bfr[ni][1]));
                    asm volatile(
                        "mma.sync.aligned.m16n8k16.row.col.f32.f16.f16.f32 "
                        "{%0,%1,%2,%3},{%4,%5,%6,%7},{%8,%9},{%0,%1,%2,%3};"
                        : "+f"(acc[mi][ni][0]), "+f"(acc[mi][ni][1]),
                          "+f"(acc[mi][ni][2]), "+f"(acc[mi][ni][3])
                        : "r"(al[0]), "r"(al[1]), "r"(al[2]), "r"(al[3]),
                          "r"(bfr[ni][0]), "r"(bfr[ni][1]));
                }
            }
        }
    }

    // ---- epilogue ----
    if (EPI == 1) {
#pragma unroll
        for (int mi = 0; mi < 4; mi++)
#pragma unroll
            for (int ni = 0; ni < 5; ni++) {
                int f = n0 + wn * 40 + ni * 8 + (lane & 3) * 2;
                float bg = bias[(size_t)e * NW + f];
                float bu = bias[(size_t)e * NW + f + 1];
#pragma unroll
                for (int hh = 0; hh < 2; hh++) {
                    int t = m0 + wm * 64 + mi * 16 + (lane >> 2) + hh * 8;
                    float gt = fminf(acc[mi][ni][hh * 2] + bg, 7.0f);
                    float up = fminf(fmaxf(acc[mi][ni][hh * 2 + 1] + bu, -7.0f), 7.0f);
                    float glu = gt / (1.0f + expf(-1.702f * gt));
                    float a = (up + 1.0f) * glu;
                    __half hv = __float2half_rn(a);
                    size_t idx = ((size_t)e * DIM_T + t) * DIM_I + (f >> 1);
                    g_act_hi[idx] = hv;
                    g_act_lo[idx] = __float2half_rn(a - __half2float(hv));
                }
            }
    } else {
#pragma unroll
        for (int mi = 0; mi < 4; mi++)
#pragma unroll
            for (int ni = 0; ni < 5; ni++) {
                int h0 = n0 + wn * 40 + ni * 8 + (lane & 3) * 2;
                float b0 = bias[(size_t)e * NW + h0];
                float b1 = bias[(size_t)e * NW + h0 + 1];
#pragma unroll
                for (int hh = 0; hh < 2; hh++) {
                    int t = m0 + wm * 64 + mi * 16 + (lane >> 2) + hh * 8;
                    float w = rw[(size_t)t * NUM_E + e];
                    float v0 = w * (acc[mi][ni][hh * 2] + b0);
                    float v1 = w * (acc[mi][ni][hh * 2 + 1] + b1);
                    asm volatile("red.global.add.v2.f32 [%0], {%1,%2};" ::"l"(
                                     &outp[(size_t)t * DIM_H + h0]),
                                 "f"(v0), "f"(v1)
                                 : "memory");
                }
            }
    }
#undef SM_AH
#undef SM_AL
#undef SM_B
}

extern "C" void kernel_launch(void* const* d_in, const int* in_sizes, int n_in,
                              void* d_out, int out_size) {
    const float* hidden = (const float*)d_in[0];
    const float* rw     = (const float*)d_in[1];
    const int4* gub     = (const int4*)d_in[2];
    const int* gus      = (const int*)d_in[3];
    const float* gubias = (const float*)d_in[4];
    const int4* db      = (const int4*)d_in[5];
    const int* ds       = (const int*)d_in[6];
    const float* dbias  = (const float*)d_in[7];
    float* out          = (float*)d_out;

    cudaFuncSetAttribute(gemm_glu<1>, cudaFuncAttributeMaxDynamicSharedMemorySize,
                         SMEM_BYTES);
    cudaFuncSetAttribute(gemm_glu<2>, cudaFuncAttributeMaxDynamicSharedMemorySize,
                         SMEM_BYTES);

    // prep: gate_up dequant + x hi/lo convert (one launch)
    k_prep<<<DEQ1_BLOCKS + CONV_BLOCKS, 256>>>(gub, gus, (const float4*)hidden);

    // GEMM1 + backfill (down-proj dequant + d_out zeroing)
    dim3 g1(G1X, G1Y, NUM_E + BF_SLICES);
    gemm_glu<1><<<g1, 256, SMEM_BYTES>>>(gubias, nullptr, out, db, ds);

    // GEMM2: vector-red accumulate into d_out
    dim3 g2(DIM_H / NT, DIM_T / 128, NUM_E);
    gemm_glu<2><<<g2, 256, SMEM_BYTES>>>(dbias, rw, out, nullptr, nullptr);
}

// round 17
// speedup vs baseline: 1.5419x; 1.5419x over previous
#include <cuda_runtime.h>
#include <cuda_fp16.h>
#include <cstdint>

#define NUM_E 8
#define DIM_H 2880
#define DIM_I 2880
#define DIM_T 1024
#define DIM_F 5760
#define NT    160

__device__ __half g_xh_hi[DIM_T * DIM_H];
__device__ __half g_xh_lo[DIM_T * DIM_H];
__device__ __half g_act_hi[(size_t)NUM_E * DIM_T * DIM_I];
__device__ __half g_act_lo[(size_t)NUM_E * DIM_T * DIM_I];
__device__ __half g_wgu[(size_t)NUM_E * DIM_F * DIM_H];
__device__ __half g_wd[(size_t)NUM_E * DIM_H * DIM_I];

__constant__ unsigned short c_fp4[16] = {
    0x0000, 0x3800, 0x3C00, 0x3E00, 0x4000, 0x4200, 0x4400, 0x4600,
    0x8000, 0xB800, 0xBC00, 0xBE00, 0xC000, 0xC200, 0xC400, 0xC600};

// Dequant body: one 256-thread block handles 256 groups of 32 weights.
__device__ __forceinline__ void deq_body(const int4* __restrict__ blk,
                                         const int* __restrict__ scl, int ngroups,
                                         int gb, __half* __restrict__ outp,
                                         void* smem) {
    __half2* lut = reinterpret_cast<__half2*>(smem);
    int t = threadIdx.x;
    lut[t] = __halves2half2(__ushort_as_half(c_fp4[t & 15]),
                            __ushort_as_half(c_fp4[(t >> 4) & 15]));
    __syncthreads();
    int g = gb * 256 + t;
    if (g >= ngroups) return;
    int row = g / 90, grp = g % 90;
    int4 v0 = blk[g * 4 + 0], v1 = blk[g * 4 + 1], v2 = blk[g * 4 + 2],
         v3 = blk[g * 4 + 3];
    int sc = scl[g];
    __half2 s2 = __half2half2(__ushort_as_half((unsigned short)((sc - 112) << 10)));
    int b[16] = {v0.x, v0.y, v0.z, v0.w, v1.x, v1.y, v1.z, v1.w,
                 v2.x, v2.y, v2.z, v2.w, v3.x, v3.y, v3.z, v3.w};
    __half2 o[16];
#pragma unroll
    for (int j = 0; j < 16; j++) o[j] = __hmul2(lut[b[j] & 255], s2);
    uint4* dst = reinterpret_cast<uint4*>(outp + (size_t)row * 2880 + grp * 32);
#pragma unroll
    for (int j = 0; j < 4; j++) dst[j] = *reinterpret_cast<uint4*>(&o[4 * j]);
}

// x -> fp16 hi/lo split; block b covers 1024 float4 (4 per thread, coalesced)
__device__ __forceinline__ void convert_body(const float4* __restrict__ x, int n4,
                                             int b) {
#pragma unroll
    for (int j = 0; j < 4; j++) {
        int i = b * 1024 + j * 256 + threadIdx.x;
        if (i < n4) {
            float4 v = x[i];
            float f[4] = {v.x, v.y, v.z, v.w};
            __half h[4], l[4];
#pragma unroll
            for (int q = 0; q < 4; q++) {
                h[q] = __float2half_rn(f[q]);
                l[q] = __float2half_rn(f[q] - __half2float(h[q]));
            }
            reinterpret_cast<__half2*>(g_xh_hi)[2 * i]     = __halves2half2(h[0], h[1]);
            reinterpret_cast<__half2*>(g_xh_hi)[2 * i + 1] = __halves2half2(h[2], h[3]);
            reinterpret_cast<__half2*>(g_xh_lo)[2 * i]     = __halves2half2(l[0], l[1]);
            reinterpret_cast<__half2*>(g_xh_lo)[2 * i + 1] = __halves2half2(l[2], l[3]);
        }
    }
}

#define DEQ1_BLOCKS 16200 /* 8*5760*90 / 256 */
#define CONV_BLOCKS 720   /* 737280 float4 / 1024 */

// Fused prep: gate_up dequant + x hi/lo convert in one launch.
__global__ __launch_bounds__(256) void k_prep(const int4* __restrict__ gub,
                                              const int* __restrict__ gus,
                                              const float4* __restrict__ x) {
    __shared__ __half2 lut[256];
    int b = blockIdx.x;
    if (b < DEQ1_BLOCKS)
        deq_body(gub, gus, NUM_E * DIM_F * 90, b, g_wgu, lut);
    else
        convert_body(x, DIM_T * DIM_H / 4, b - DEQ1_BLOCKS);
}

// ---------------------------------------------------------------------------
// HMMA GEMM: pre-dequant fp16 B, split-precision A (hi+lo), 3-stage cp.async,
// single sync per k-tile, warp-parity kk/load stagger. Tile 128x160x32,
// 8 warps (2M x 4N), warp 64x40, 2 CTAs/SM.
// EPI==1: GLU -> g_act hi/lo; backfill z-slices: down-proj dequant + d_out zero.
// EPI==2: scalar atomicAdd (REDG-class, proven fast) into d_out.
// ---------------------------------------------------------------------------
#define LDS 40
#define SMEM_BYTES ((2 * 128 + NT) * LDS * 2 * 3)
#define DEQ2_BLOCKS 8100  /* 8*2880*90 / 256 */
#define ZERO_BLOCKS 720   /* 737280 float4 / 1024 */
#define G1X 36            /* DIM_F / NT */
#define G1Y 8             /* DIM_T / 128 */
#define BF_TOTAL (DEQ2_BLOCKS + ZERO_BLOCKS)
#define BF_SLICES 31      /* ceil(8820 / 288) */

template <int EPI>
__global__ __launch_bounds__(256, 2) void gemm_glu(const float* __restrict__ bias,
                                                   const float* __restrict__ rw,
                                                   float* __restrict__ outp,
                                                   const int4* __restrict__ dblk,
                                                   const int* __restrict__ dscl) {
    constexpr int NW = (EPI == 1) ? DIM_F : DIM_H;
    constexpr int K  = 2880;
    constexpr int KT = K / 32;  // 90

    extern __shared__ __align__(16) char smem_raw[];

    if (EPI == 1 && blockIdx.z >= NUM_E) {
        int b = (blockIdx.z - NUM_E) * (G1X * G1Y) + blockIdx.y * G1X + blockIdx.x;
        if (b < DEQ2_BLOCKS) {
            deq_body(dblk, dscl, NUM_E * DIM_H * 90, b, g_wd, smem_raw);
        } else if (b < BF_TOTAL) {
            int zb = b - DEQ2_BLOCKS;
            float4* o4 = reinterpret_cast<float4*>(outp);
#pragma unroll
            for (int j = 0; j < 4; j++) {
                int i = zb * 1024 + j * 256 + threadIdx.x;
                if (i < DIM_T * DIM_H / 4) o4[i] = make_float4(0.f, 0.f, 0.f, 0.f);
            }
        }
        return;
    }

    const int e    = blockIdx.z;
    const int n0   = blockIdx.x * NT;
    const int m0   = blockIdx.y * 128;
    const int tid  = threadIdx.x;
    const int lane = tid & 31;
    const int wid  = tid >> 5;
    const int wm   = wid >> 2;
    const int wn   = wid & 3;
    const int wpar = wid & 1;

    __half* AsH = reinterpret_cast<__half*>(smem_raw);
    __half* AsL = AsH + 3 * 128 * LDS;
    __half* Bs  = AsL + 3 * 128 * LDS;

#define SM_AH(s, r, c) AsH[((s)*128 + (r)) * LDS + (c)]
#define SM_AL(s, r, c) AsL[((s)*128 + (r)) * LDS + (c)]
#define SM_B(s, r, c)  Bs[((s)*NT + (r)) * LDS + (c)]

    const __half* AgH = (EPI == 1) ? g_xh_hi : g_act_hi + (size_t)e * DIM_T * K;
    const __half* AgL = (EPI == 1) ? g_xh_lo : g_act_lo + (size_t)e * DIM_T * K;
    const __half* BW  = ((EPI == 1) ? g_wgu : g_wd) + ((size_t)e * NW + n0) * K;

    auto load_A = [&](int st, int kt) {
#pragma unroll
        for (int i = tid; i < 512; i += 256) {
            int r = i >> 2, c = (i & 3) * 8;
            unsigned dh = (unsigned)__cvta_generic_to_shared(&SM_AH(st, r, c));
            asm volatile("cp.async.cg.shared.global [%0],[%1],16;" ::"r"(dh),
                         "l"(AgH + (size_t)(m0 + r) * K + kt * 32 + c));
            unsigned dl = (unsigned)__cvta_generic_to_shared(&SM_AL(st, r, c));
            asm volatile("cp.async.cg.shared.global [%0],[%1],16;" ::"r"(dl),
                         "l"(AgL + (size_t)(m0 + r) * K + kt * 32 + c));
        }
    };
    auto load_B = [&](int st, int kt) {
#pragma unroll 1
        for (int i = tid; i < NT * 4; i += 256) {
            int r = i >> 2, c = (i & 3) * 8;
            unsigned db = (unsigned)__cvta_generic_to_shared(&SM_B(st, r, c));
            asm volatile("cp.async.cg.shared.global [%0],[%1],16;" ::"r"(db),
                         "l"(BW + (size_t)r * K + kt * 32 + c));
        }
    };
    auto load_stage = [&](int st, int kt) {
        if (wpar) {
            load_B(st, kt);
            load_A(st, kt);
        } else {
            load_A(st, kt);
            load_B(st, kt);
        }
        asm volatile("cp.async.commit_group;");
    };

    float acc[4][5][4];
#pragma unroll
    for (int i = 0; i < 4; i++)
#pragma unroll
        for (int j = 0; j < 5; j++)
#pragma unroll
            for (int c = 0; c < 4; c++) acc[i][j][c] = 0.f;

    const int brow = wn * 40 + (lane & 7);
    const int bcol = ((lane >> 3) & 1) * 8;
    const int arow = wm * 64 + (lane & 15);
    const int acol = (lane >> 4) * 8;

    load_stage(0, 0);
    load_stage(1, 1);

#pragma unroll 1
    for (int kt = 0; kt < KT; ++kt) {
        const int cur = kt % 3;
        if (kt + 1 < KT)
            asm volatile("cp.async.wait_group 1;");
        else
            asm volatile("cp.async.wait_group 0;");
        __syncthreads();
        if (kt + 2 < KT) load_stage((kt + 2) % 3, kt + 2);

#pragma unroll
        for (int kx = 0; kx < 2; ++kx) {
            const int kk = kx ^ wpar;  // warp-parity stagger: anti-phase LDSM
            unsigned bfr[5][2];
#pragma unroll
            for (int ni = 0; ni < 5; ni++) {
                unsigned sa = (unsigned)__cvta_generic_to_shared(
                    &SM_B(cur, brow + ni * 8, kk * 16 + bcol));
                asm volatile("ldmatrix.sync.aligned.m8n8.x2.shared.b16 {%0,%1},[%2];"
                             : "=r"(bfr[ni][0]), "=r"(bfr[ni][1])
                             : "r"(sa));
            }
#pragma unroll
            for (int mi = 0; mi < 4; mi++) {
                unsigned ah[4], al[4];
                unsigned sh = (unsigned)__cvta_generic_to_shared(
                    &SM_AH(cur, arow + mi * 16, kk * 16 + acol));
                asm volatile("ldmatrix.sync.aligned.m8n8.x4.shared.b16 {%0,%1,%2,%3},[%4];"
                             : "=r"(ah[0]), "=r"(ah[1]), "=r"(ah[2]), "=r"(ah[3])
                             : "r"(sh));
                unsigned sl = (unsigned)__cvta_generic_to_shared(
                    &SM_AL(cur, arow + mi * 16, kk * 16 + acol));
                asm volatile("ldmatrix.sync.aligned.m8n8.x4.shared.b16 {%0,%1,%2,%3},[%4];"
                             : "=r"(al[0]), "=r"(al[1]), "=r"(al[2]), "=r"(al[3])
                             : "r"(sl));
#pragma unroll
                for (int ni = 0; ni < 5; ni++) {
                    asm volatile(
                        "mma.sync.aligned.m16n8k16.row.col.f32.f16.f16.f32 "
                        "{%0,%1,%2,%3},{%4,%5,%6,%7},{%8,%9},{%0,%1,%2,%3};"
                        : "+f"(acc[mi][ni][0]), "+f"(acc[mi][ni][1]),
                          "+f"(acc[mi][ni][2]), "+f"(acc[mi][ni][3])
                        : "r"(ah[0]), "r"(ah[1]), "r"(ah[2]), "r"(ah[3]),
                          "r"(bfr[ni][0]), "r"(bfr[ni][1]));
                    asm volatile(
                        "mma.sync.aligned.m16n8k16.row.col.f32.f16.f16.f32 "
                        "{%0,%1,%2,%3},{%4,%5,%6,%7},{%8,%9},{%0,%1,%2,%3};"
                        : "+f"(acc[mi][ni][0]), "+f"(acc[mi][ni][1]),
                          "+f"(acc[mi][ni][2]), "+f"(acc[mi][ni][3])
                        : "r"(al[0]), "r"(al[1]), "r"(al[2]), "r"(al[3]),
                          "r"(bfr[ni][0]), "r"(bfr[ni][1]));
                }
            }
        }
    }

    // ---- epilogue ----
    if (EPI == 1) {
#pragma unroll
        for (int mi = 0; mi < 4; mi++)
#pragma unroll
            for (int ni = 0; ni < 5; ni++) {
                int f = n0 + wn * 40 + ni * 8 + (lane & 3) * 2;
                float bg = bias[(size_t)e * NW + f];
                float bu = bias[(size_t)e * NW + f + 1];
#pragma unroll
                for (int hh = 0; hh < 2; hh++) {
                    int t = m0 + wm * 64 + mi * 16 + (lane >> 2) + hh * 8;
                    float gt = fminf(acc[mi][ni][hh * 2] + bg, 7.0f);
                    float up = fminf(fmaxf(acc[mi][ni][hh * 2 + 1] + bu, -7.0f), 7.0f);
                    float glu = gt / (1.0f + expf(-1.702f * gt));
                    float a = (up + 1.0f) * glu;
                    __half hv = __float2half_rn(a);
                    size_t idx = ((size_t)e * DIM_T + t) * DIM_I + (f >> 1);
                    g_act_hi[idx] = hv;
                    g_act_lo[idx] = __float2half_rn(a - __half2float(hv));
                }
            }
    } else {
#pragma unroll
        for (int mi = 0; mi < 4; mi++)
#pragma unroll
            for (int ni = 0; ni < 5; ni++) {
                int h0 = n0 + wn * 40 + ni * 8 + (lane & 3) * 2;
                float b0 = bias[(size_t)e * NW + h0];
                float b1 = bias[(size_t)e * NW + h0 + 1];
#pragma unroll
                for (int hh = 0; hh < 2; hh++) {
                    int t = m0 + wm * 64 + mi * 16 + (lane >> 2) + hh * 8;
                    float w = rw[(size_t)t * NUM_E + e];
                    atomicAdd(&outp[(size_t)t * DIM_H + h0],
                              w * (acc[mi][ni][hh * 2] + b0));
                    atomicAdd(&outp[(size_t)t * DIM_H + h0 + 1],
                              w * (acc[mi][ni][hh * 2 + 1] + b1));
                }
            }
    }
#undef SM_AH
#undef SM_AL
#undef SM_B
}

extern "C" void kernel_launch(void* const* d_in, const int* in_sizes, int n_in,
                              void* d_out, int out_size) {
    const float* hidden = (const float*)d_in[0];
    const float* rw     = (const float*)d_in[1];
    const int4* gub     = (const int4*)d_in[2];
    const int* gus      = (const int*)d_in[3];
    const float* gubias = (const float*)d_in[4];
    const int4* db      = (const int4*)d_in[5];
    const int* ds       = (const int*)d_in[6];
    const float* dbias  = (const float*)d_in[7];
    float* out          = (float*)d_out;

    cudaFuncSetAttribute(gemm_glu<1>, cudaFuncAttributeMaxDynamicSharedMemorySize,
                         SMEM_BYTES);
    cudaFuncSetAttribute(gemm_glu<2>, cudaFuncAttributeMaxDynamicSharedMemorySize,
                         SMEM_BYTES);

    // prep: gate_up dequant + x hi/lo convert (one launch)
    k_prep<<<DEQ1_BLOCKS + CONV_BLOCKS, 256>>>(gub, gus, (const float4*)hidden);

    // GEMM1 + backfill (down-proj dequant + d_out zeroing)
    dim3 g1(G1X, G1Y, NUM_E + BF_SLICES);
    gemm_glu<1><<<g1, 256, SMEM_BYTES>>>(gubias, nullptr, out, db, ds);

    // GEMM2: scalar atomicAdd accumulate into d_out
    dim3 g2(DIM_H / NT, DIM_T / 128, NUM_E);
    gemm_glu<2><<<g2, 256, SMEM_BYTES>>>(dbias, rw, out, nullptr, nullptr);
}